// round 17
// baseline (speedup 1.0000x reference)
#include <cuda_runtime.h>
#include <cuda_fp16.h>
#include <cstdint>

#define NC 5
#define NU 6144
#define NV 6144
#define ND 64
#define NB 4096
#define CAPM 448   // merged per-node list capacity: mean 307, sigma 17.4 -> 8 sigma

// ---------------- scratch (static device globals; no runtime allocation) ----
__device__ __align__(16) __half g_msg_a[NC * NV * ND];   // fp16 messages [C,V,D]
__device__ __align__(16) __half g_msg_b[NC * NU * ND];   // fp16 messages [C,U,D]
__device__ __align__(16) float g_hu[NU * ND];
__device__ __align__(16) float g_hv[NV * ND];
__device__ __align__(16) float g_zu[NU * ND];
__device__ __align__(16) float g_zv[NV * ND];
// cursors: zero at load; re-zeroed by k_dec every run
__device__ int g_rowcnt[NU];
__device__ int g_colcnt[NV];
__device__ __align__(16) unsigned short g_rowlist[NU * CAPM];  // value = c*NV+v
__device__ __align__(16) unsigned short g_collist[NV * CAPM];  // value = c*NU+u

// ---------------- bit-cast helpers ------------------------------------------
__device__ __forceinline__ unsigned h2u(half2 h) {
    return *reinterpret_cast<unsigned*>(&h);
}
__device__ __forceinline__ half2 u2h(unsigned u) {
    return *reinterpret_cast<half2*>(&u);
}
__device__ __forceinline__ uint32_t smem_u32(const void* p) {
    uint32_t a;
    asm("{ .reg .u64 t; cvta.to.shared.u64 t, %1; cvt.u32.u64 %0, t; }" : "=r"(a) : "l"(p));
    return a;
}
__device__ __forceinline__ void cpa16(uint32_t dst, const void* src) {
    asm volatile("cp.async.cg.shared.global [%0], [%1], 16;" :: "r"(dst), "l"(src) : "memory");
}

// ---------------- adjacency build: cp.async-staged, per-lane extraction -----
#define NTILE  737280u   // (NC*NU*NV)/256
#define TPC    147456u   // (NU*NV)/256 tiles per class
#define TPR    24u       // tiles per adjacency row (6144/256)
#define DEPTH  6         // smem pipeline stages per warp (6 x 1KB)

#define T1_BLKS    960u
#define BUILD_BLKS 1184u
#define FUSED_GRID (T1_BLKS + BUILD_BLKS)
#define SMEM_FUSED (8 * DEPTH * 1024)   // 48KB: 8 warps x 6 stages x 1KB

__device__ __forceinline__ void process_tile(unsigned tile, unsigned long long a,
                                             unsigned long long b, unsigned long long c,
                                             unsigned long long d, int lane) {
    if ((a | b | c | d) == 0ull) return;   // fast path: 92% of lanes

    unsigned msk = 0;
    msk |= ((unsigned)a         != 0u) ? 0x01u : 0u;
    msk |= ((unsigned)(a >> 32) != 0u) ? 0x02u : 0u;
    msk |= ((unsigned)b         != 0u) ? 0x04u : 0u;
    msk |= ((unsigned)(b >> 32) != 0u) ? 0x08u : 0u;
    msk |= ((unsigned)c         != 0u) ? 0x10u : 0u;
    msk |= ((unsigned)(c >> 32) != 0u) ? 0x20u : 0u;
    msk |= ((unsigned)d         != 0u) ? 0x40u : 0u;
    msk |= ((unsigned)(d >> 32) != 0u) ? 0x80u : 0u;

    unsigned cls = tile / TPC;
    unsigned rt  = tile - cls * TPC;          // tile within class
    unsigned uu  = rt / TPR;                  // constant row for the tile
    unsigned vb  = (rt - uu * TPR) * 256u + (unsigned)lane * 8u;
    unsigned crow = cls * (unsigned)NV;
    unsigned ccol = cls * (unsigned)NU;

    int cnt = __popc(msk);
    int s = atomicAdd(&g_rowcnt[uu], cnt);    // one aggregated row atomic/lane
    unsigned rl = uu * CAPM;
    while (msk) {
        int k = __ffs(msk) - 1;
        msk &= msk - 1u;
        unsigned vv = vb + (unsigned)k;
        if (s < CAPM) g_rowlist[rl + s] = (unsigned short)(crow + vv);
        s++;
        int q = atomicAdd(&g_colcnt[vv], 1);
        if (q < CAPM) g_collist[vv * CAPM + q] = (unsigned short)(ccol + uu);
    }
}

// cp.async smem ring: DEPTH-1 tiles in flight ahead of processing, no regs
__device__ void build_body(const float* __restrict__ adj, unsigned bbid, char* dsm) {
    int lane = threadIdx.x & 31;
    int wrp = threadIdx.x >> 5;
    uint32_t sbase = smem_u32(dsm) + (uint32_t)wrp * (DEPTH * 1024u) + (uint32_t)lane * 32u;
    const char* gbase = (const char*)adj + (unsigned)lane * 32u;
    unsigned warp = (bbid * 256u + threadIdx.x) >> 5;
    const unsigned nwarp = (BUILD_BLKS * 256u) >> 5;   // 9472

    // prologue: issue DEPTH-1 stages
#pragma unroll
    for (int i = 0; i < DEPTH - 1; i++) {
        unsigned t = warp + (unsigned)i * nwarp;
        if (t < NTILE) {
            cpa16(sbase + (uint32_t)i * 1024u, gbase + (size_t)t * 1024u);
            cpa16(sbase + (uint32_t)i * 1024u + 16u, gbase + (size_t)t * 1024u + 16u);
        }
        asm volatile("cp.async.commit_group;" ::: "memory");
    }

    unsigned t = warp;
    int s = 0;
    while (t < NTILE) {
        unsigned tn = t + (unsigned)(DEPTH - 1) * nwarp;
        int sn = s + (DEPTH - 1);
        if (sn >= DEPTH) sn -= DEPTH;
        if (tn < NTILE) {
            cpa16(sbase + (uint32_t)sn * 1024u, gbase + (size_t)tn * 1024u);
            cpa16(sbase + (uint32_t)sn * 1024u + 16u, gbase + (size_t)tn * 1024u + 16u);
        }
        asm volatile("cp.async.commit_group;" ::: "memory");
        asm volatile("cp.async.wait_group %0;" :: "n"(DEPTH - 2) : "memory");

        unsigned long long a, b, c, d;
        asm volatile("ld.shared.v2.u64 {%0, %1}, [%2];"
                     : "=l"(a), "=l"(b) : "r"(sbase + (uint32_t)s * 1024u));
        asm volatile("ld.shared.v2.u64 {%0, %1}, [%2];"
                     : "=l"(c), "=l"(d) : "r"(sbase + (uint32_t)s * 1024u + 16u));
        process_tile(t, a, b, c, d, lane);

        t += nwarp;
        if (++s == DEPTH) s = 0;
    }
}

// ---------------- per-class dense transform body (fp16 out) -----------------
// Xs/Ws live in the caller-provided shared buffer.
__device__ __forceinline__ void transform_body(
    int bx, int c, int z, float* Xs, float* Ws,
    const float* __restrict__ X0, const float* __restrict__ W0, __half* __restrict__ out0,
    const float* __restrict__ X1, const float* __restrict__ W1, __half* __restrict__ out1,
    int N) {
    int tid = threadIdx.x;               // 256 threads
    int n0 = bx * 64;
    const float* X = (z == 0) ? X0 : X1;
    const float* W = (z == 0) ? W0 : W1;
    __half* out = (z == 0) ? out0 : out1;

    const float4* X4 = (const float4*)(X + (size_t)n0 * ND);
    const float4* W4 = (const float4*)(W + (size_t)c * ND * ND);
#pragma unroll
    for (int r = 0; r < 4; r++) {
        int f = tid + r * 256;
        float4 xv = X4[f];
        int n = f >> 4, q = f & 15;
        Xs[n * 65 + 4 * q + 0] = xv.x;
        Xs[n * 65 + 4 * q + 1] = xv.y;
        Xs[n * 65 + 4 * q + 2] = xv.z;
        Xs[n * 65 + 4 * q + 3] = xv.w;
        ((float4*)Ws)[f] = W4[f];
    }
    __syncthreads();

    int te = tid & 15, tn = tid >> 4;
    float a00=0,a01=0,a02=0,a03=0, a10=0,a11=0,a12=0,a13=0;
    float a20=0,a21=0,a22=0,a23=0, a30=0,a31=0,a32=0,a33=0;
#pragma unroll 8
    for (int d = 0; d < 64; d++) {
        float4 w = *(const float4*)&Ws[d * 64 + te * 4];
        float x0 = Xs[(tn * 4 + 0) * 65 + d];
        float x1 = Xs[(tn * 4 + 1) * 65 + d];
        float x2 = Xs[(tn * 4 + 2) * 65 + d];
        float x3 = Xs[(tn * 4 + 3) * 65 + d];
        a00 += x0 * w.x; a01 += x0 * w.y; a02 += x0 * w.z; a03 += x0 * w.w;
        a10 += x1 * w.x; a11 += x1 * w.y; a12 += x1 * w.z; a13 += x1 * w.w;
        a20 += x2 * w.x; a21 += x2 * w.y; a22 += x2 * w.z; a23 += x2 * w.w;
        a30 += x3 * w.x; a31 += x3 * w.y; a32 += x3 * w.z; a33 += x3 * w.w;
    }
    __half* ob = out + ((size_t)c * N + n0 + tn * 4) * ND + te * 4;
    *(uint2*)(ob + 0 * ND) = make_uint2(h2u(__floats2half2_rn(a00, a01)),
                                        h2u(__floats2half2_rn(a02, a03)));
    *(uint2*)(ob + 1 * ND) = make_uint2(h2u(__floats2half2_rn(a10, a11)),
                                        h2u(__floats2half2_rn(a12, a13)));
    *(uint2*)(ob + 2 * ND) = make_uint2(h2u(__floats2half2_rn(a20, a21)),
                                        h2u(__floats2half2_rn(a22, a23)));
    *(uint2*)(ob + 3 * ND) = make_uint2(h2u(__floats2half2_rn(a30, a31)),
                                        h2u(__floats2half2_rn(a32, a33)));
}

// ---------------- fused: adjacency build + layer-1 transforms ---------------
__global__ void __launch_bounds__(256, 4)
k_fused1(const float* __restrict__ adj,
         const float* __restrict__ Xv, const float* __restrict__ W1v, __half* __restrict__ msg_a,
         const float* __restrict__ Xu, const float* __restrict__ W1u, __half* __restrict__ msg_b) {
    extern __shared__ __align__(16) char dsm[];
    unsigned bid = blockIdx.x;
    bool is_t = (bid < 2u * T1_BLKS) && ((bid & 1u) == 0u);
    if (is_t) {
        unsigned tb = bid >> 1;                 // 0..959
        int bx = tb % 96;
        unsigned r = tb / 96;
        int c = r % NC, z = r / NC;
        transform_body(bx, c, z, (float*)dsm, (float*)(dsm + 64 * 65 * 4),
                       Xv, W1v, msg_a, Xu, W1u, msg_b, NV);
    } else {
        unsigned bb = (bid < 2u * T1_BLKS) ? (bid >> 1) : (bid - T1_BLKS);
        build_body(adj, bb, dsm);
    }
}

// ---------------- standalone transform (layer 2) ----------------------------
__global__ void k_transform2(const float* __restrict__ X0, const float* __restrict__ W0,
                             __half* __restrict__ out0,
                             const float* __restrict__ X1, const float* __restrict__ W1,
                             __half* __restrict__ out1, int N) {
    __shared__ __align__(16) float Xs[64 * 65];
    __shared__ __align__(16) float Ws[64 * 64];
    transform_body(blockIdx.x, blockIdx.y, blockIdx.z, Xs, Ws, X0, W0, out0, X1, W1, out1, N);
}

// ---------------- merged sparse aggregation over fp16 messages --------------
__device__ __forceinline__ void hacc(float4& a, uint2 p) {
    float2 lo = __half22float2(u2h(p.x));
    float2 hi = __half22float2(u2h(p.y));
    a.x += lo.x; a.y += lo.y; a.z += hi.x; a.w += hi.y;
}

__global__ void k_gather2(float* __restrict__ outA, const __half* __restrict__ msgA,
                          const float* __restrict__ biasA,
                          float* __restrict__ outB, const __half* __restrict__ msgB,
                          const float* __restrict__ biasB, int do_relu) {
    __shared__ __align__(16) unsigned short sidx[4][CAPM];
    int warp = threadIdx.x >> 5, lane = threadIdx.x & 31;
    int node = blockIdx.x * 4 + warp;
    bool sideA = node < NU;
    int u = sideA ? node : node - NU;
    const __half* msg = sideA ? msgA : msgB;
    const float* bias = sideA ? biasA : biasB;
    float* out = sideA ? outA : outB;
    const int* cnt = sideA ? g_rowcnt : g_colcnt;
    const unsigned short* lists = sideA ? g_rowlist : g_collist;

    int m = cnt[u];
    if (m > CAPM) m = CAPM;

    const uint4* lg = (const uint4*)(lists + (size_t)u * CAPM);
    uint4* ls = (uint4*)sidx[warp];
    for (int k = lane; k * 8 < m; k += 32) ls[k] = lg[k];
    __syncwarp();

    int hw = lane >> 4;
    int l4 = lane & 15;
    float4 acc = make_float4(0.f, 0.f, 0.f, 0.f);
    if (hw == 0) {
#pragma unroll
        for (int c = 0; c < NC; c++) {
            float4 bv = ((const float4*)(bias + c * ND))[l4];
            acc.x += bv.x; acc.y += bv.y; acc.z += bv.z; acc.w += bv.w;
        }
    }

    const uint2* mg = (const uint2*)msg;
    const unsigned short* si = sidx[warp];
    int mm = m & ~7;
    for (int b = 0; b < mm; b += 8) {
        unsigned o0 = si[b + 0 + hw];
        unsigned o1 = si[b + 2 + hw];
        unsigned o2 = si[b + 4 + hw];
        unsigned o3 = si[b + 6 + hw];
        uint2 p0 = mg[o0 * 16u + l4];
        uint2 p1 = mg[o1 * 16u + l4];
        uint2 p2 = mg[o2 * 16u + l4];
        uint2 p3 = mg[o3 * 16u + l4];
        hacc(acc, p0); hacc(acc, p1); hacc(acc, p2); hacc(acc, p3);
    }
    for (int b = mm; b < m; b += 2) {
        int e = b + hw;
        if (e < m) {
            uint2 p = mg[(unsigned)si[e] * 16u + l4];
            hacc(acc, p);
        }
    }
    acc.x += __shfl_xor_sync(0xffffffffu, acc.x, 16);
    acc.y += __shfl_xor_sync(0xffffffffu, acc.y, 16);
    acc.z += __shfl_xor_sync(0xffffffffu, acc.z, 16);
    acc.w += __shfl_xor_sync(0xffffffffu, acc.w, 16);
    if (hw == 0) {
        if (do_relu) {
            acc.x = fmaxf(acc.x, 0.f); acc.y = fmaxf(acc.y, 0.f);
            acc.z = fmaxf(acc.z, 0.f); acc.w = fmaxf(acc.w, 0.f);
        }
        ((float4*)(out + (size_t)u * ND))[l4] = acc;
    }
}

// ---------------- fused decoder: (zu[ui] @ Q[c]) . zv[vi] -> logits ---------
// Also re-zeroes the build cursors (last kernel; globals start zeroed at load).
__global__ void k_dec(const float* __restrict__ Q, const int* __restrict__ ui,
                      const int* __restrict__ vi, float* __restrict__ out) {
    int zb = blockIdx.y * 64 + blockIdx.x;        // grid (64, 5) -> 320 blocks
    if (zb < 24)      g_rowcnt[zb * 256 + threadIdx.x] = 0;        // 24*256 = 6144
    else if (zb < 48) g_colcnt[(zb - 24) * 256 + threadIdx.x] = 0;

    __shared__ __align__(16) float Xs[64 * 65];
    __shared__ __align__(16) float Ws[64 * 64];
    int tid = threadIdx.x;
    int c = blockIdx.y;
    int n0 = blockIdx.x * 64;

    const float4* W4 = (const float4*)(Q + (size_t)c * ND * ND);
#pragma unroll
    for (int r = 0; r < 4; r++) {
        int f = tid + r * 256;
        int n = f >> 4, q = f & 15;
        int row = ui[n0 + n];
        float4 xv = ((const float4*)(g_zu + (size_t)row * ND))[q];
        Xs[n * 65 + 4 * q + 0] = xv.x;
        Xs[n * 65 + 4 * q + 1] = xv.y;
        Xs[n * 65 + 4 * q + 2] = xv.z;
        Xs[n * 65 + 4 * q + 3] = xv.w;
        ((float4*)Ws)[f] = W4[f];
    }
    __syncthreads();

    int te = tid & 15, tn = tid >> 4;
    float a00=0,a01=0,a02=0,a03=0, a10=0,a11=0,a12=0,a13=0;
    float a20=0,a21=0,a22=0,a23=0, a30=0,a31=0,a32=0,a33=0;
#pragma unroll 8
    for (int d = 0; d < 64; d++) {
        float4 w = *(const float4*)&Ws[d * 64 + te * 4];
        float x0 = Xs[(tn * 4 + 0) * 65 + d];
        float x1 = Xs[(tn * 4 + 1) * 65 + d];
        float x2 = Xs[(tn * 4 + 2) * 65 + d];
        float x3 = Xs[(tn * 4 + 3) * 65 + d];
        a00 += x0 * w.x; a01 += x0 * w.y; a02 += x0 * w.z; a03 += x0 * w.w;
        a10 += x1 * w.x; a11 += x1 * w.y; a12 += x1 * w.z; a13 += x1 * w.w;
        a20 += x2 * w.x; a21 += x2 * w.y; a22 += x2 * w.z; a23 += x2 * w.w;
        a30 += x3 * w.x; a31 += x3 * w.y; a32 += x3 * w.z; a33 += x3 * w.w;
    }
#pragma unroll
    for (int r = 0; r < 4; r++) {
        int b = n0 + tn * 4 + r;
        int v = vi[b];
        float4 zvv = ((const float4*)(g_zv + (size_t)v * ND))[te];
        float p;
        if (r == 0)      p = a00 * zvv.x + a01 * zvv.y + a02 * zvv.z + a03 * zvv.w;
        else if (r == 1) p = a10 * zvv.x + a11 * zvv.y + a12 * zvv.z + a13 * zvv.w;
        else if (r == 2) p = a20 * zvv.x + a21 * zvv.y + a22 * zvv.z + a23 * zvv.w;
        else             p = a30 * zvv.x + a31 * zvv.y + a32 * zvv.z + a33 * zvv.w;
#pragma unroll
        for (int o = 8; o; o >>= 1) p += __shfl_xor_sync(0xffffffffu, p, o);
        if (te == 0) out[b * NC + c] = p;
    }
}

// ---------------- launcher ---------------------------------------------------
extern "C" void kernel_launch(void* const* d_in, const int* in_sizes, int n_in,
                              void* d_out, int out_size) {
    const int*   ui    = (const int*)d_in[0];
    const int*   vi    = (const int*)d_in[1];
    const float* u_emb = (const float*)d_in[2];
    const float* v_emb = (const float*)d_in[3];
    const float* W1u   = (const float*)d_in[4];
    const float* b1u   = (const float*)d_in[5];
    const float* W1v   = (const float*)d_in[6];
    const float* b1v   = (const float*)d_in[7];
    const float* W2u   = (const float*)d_in[8];
    const float* b2u   = (const float*)d_in[9];
    const float* W2v   = (const float*)d_in[10];
    const float* b2v   = (const float*)d_in[11];
    const float* Q     = (const float*)d_in[12];
    const float* adj   = (const float*)d_in[13];
    float* out = (float*)d_out;

    __half *msg_a, *msg_b;
    float *hu, *hv, *zu, *zv;
    cudaGetSymbolAddress((void**)&msg_a, g_msg_a);
    cudaGetSymbolAddress((void**)&msg_b, g_msg_b);
    cudaGetSymbolAddress((void**)&hu, g_hu);
    cudaGetSymbolAddress((void**)&hv, g_hv);
    cudaGetSymbolAddress((void**)&zu, g_zu);
    cudaGetSymbolAddress((void**)&zv, g_zv);

    // idempotent attribute set (not a stream op; safe under graph capture)
    cudaFuncSetAttribute(k_fused1, cudaFuncAttributeMaxDynamicSharedMemorySize, SMEM_FUSED);

    // fused build (cp.async 6-deep smem pipeline) + layer-1 transforms
    k_fused1<<<FUSED_GRID, 256, SMEM_FUSED>>>(adj, v_emb, W1v, msg_a, u_emb, W1u, msg_b);

    // layer 1 gather
    k_gather2<<<(NU + NV) / 4, 128>>>(hu, msg_a, b1v, hv, msg_b, b1u, 1);

    // layer 2
    k_transform2<<<dim3(96, NC, 2), 256>>>(hv, W2u, msg_a, hu, W2v, msg_b, NV);
    k_gather2<<<(NU + NV) / 4, 128>>>(zu, msg_a, b2u, zv, msg_b, b2v, 0);

    // fused bilinear decoder (also re-zeroes cursors for the next run)
    k_dec<<<dim3(64, NC), 256>>>(Q, ui, vi, out);
}